// round 6
// baseline (speedup 1.0000x reference)
#include <cuda_runtime.h>
#include <cuda_fp16.h>
#include <math.h>

#define NPOS 392
#define KK   288          // K*K*IN_CAPS
#define OC   32
#define PS   16
#define OSZ  512          // OC*PS
#define CEPS 1e-8f
#define LN2PI 1.8378770664093453f
#define NT   384          // 12 warps; 2 CTAs/SM -> 80-reg ceiling

// vote scratch (fp16): 392 * 288 * 512 * 2B = 115.6 MB
__device__ __half g_votes[(size_t)NPOS * KK * OSZ];

extern __shared__ float smem[];

__device__ __forceinline__ void stats_phase(
    int tid, const float* Mb, const float* Qb,
    const float* rsArr, float rsUni, float lam,
    float* sMean, float* sIv, float* sAct, float* sC,
    const float* __restrict__ beta_u, const float* __restrict__ beta_a)
{
    if (tid < 256) {
        const int o  = tid >> 3;
        const int sp = tid & 7;
        float rs  = rsArr ? rsArr[o] : rsUni;
        float irs = 1.f/(rs + CEPS);
        float s1  = rs/(rs + CEPS);
        float M0 = Mb[o*16 + 2*sp]   * irs;
        float M1 = Mb[o*16 + 2*sp+1] * irs;
        float Q0 = Qb[o*16 + 2*sp]   * irs;
        float Q1 = Qb[o*16 + 2*sp+1] * irs;
        // sum r*(v-mean)^2 = Q - mean^2*(2 - S1)   (exact EPS algebra)
        float v0 = fmaxf(Q0 - M0*M0*(2.f - s1), 0.f) + CEPS;
        float v1 = fmaxf(Q1 - M1*M1*(2.f - s1), 0.f) + CEPS;
        sMean[o*17 + 2*sp]   = M0;
        sMean[o*17 + 2*sp+1] = M1;
        sIv[o*17 + 2*sp]     = 0.5f/v0;
        sIv[o*17 + 2*sp+1]   = 0.5f/v1;
        float sl = 0.5f*(__logf(v0) + __logf(v1));
        #pragma unroll
        for (int off = 1; off < 8; off <<= 1)
            sl += __shfl_xor_sync(0xffffffffu, sl, off);
        if (sp == 0) {
            float cost = (16.f*beta_u[o] + sl) * rs;
            float z = lam * (beta_a[o] - cost);
            float a = 1.f/(1.f + __expf(-z));
            sAct[o] = a;
            sC[o]   = __logf(a) - sl - 8.f*LN2PI;
        }
    }
}

__global__ __launch_bounds__(NT, 2)
void convcaps_kernel(const float* __restrict__ x,
                     const float* __restrict__ wts,
                     const float* __restrict__ beta_u,
                     const float* __restrict__ beta_a,
                     float* __restrict__ out)
{
    const int n    = blockIdx.x;
    const int tid  = threadIdx.x;
    const int o    = tid & 31;     // output-capsule lane (warp = 32 o's)
    const int kg   = tid >> 5;     // k-group 0..11

    // ---- smem carve (~32.6 KB) ----
    float* sP    = smem;            // 4608  poses [k][s]
    float* sCk   = sP + KK*PS;      // 288   ck = a/(a+eps)
    float* sM0   = sCk + KK;        // 512
    float* sQ0   = sM0 + 512;       // 512
    float* sM1   = sQ0 + 512;       // 512
    float* sQ1   = sM1 + 512;       // 512
    float* sMean = sQ1 + 512;       // 544   [o*17+s]
    float* sIv   = sMean + 544;     // 544
    float* sRs1  = sIv + 544;       // 32    rsum from fused pass 1
    float* sRs2  = sRs1 + 32;       // 32    rsum from fused pass 2
    float* sAct  = sRs2 + 32;       // 32
    float* sC    = sAct + 32;       // 32
    float* sCkS  = sC + 32;         // 1

    // ---- zero accumulators ----
    for (int i = tid; i < 2048; i += NT) sM0[i] = 0.f;   // sM0..sQ1 contiguous
    if (tid < 64) sRs1[tid] = 0.f;
    if (tid == 64) *sCkS = 0.f;
    __syncthreads();

    // ---- Phase 0: gather input tile (reference reshape semantics) ----
    const int b = n / 49;
    const int m = n - b*49;
    for (int idx = tid; idx < 9*544; idx += NT) {
        int j   = idx / 544;
        int c   = idx - j*544;
        int t9  = 9*m + j;
        int khw = t9 / 49;
        int oyx = t9 - khw*49;
        int oy  = oyx / 7;
        int ox  = oyx - oy*7;
        int kh  = khw / 3;
        int kw  = khw - kh*3;
        int h   = 2*oy + kh;
        int w   = 2*ox + kw;
        float v = x[(size_t)(((b*16 + h)*16) + w)*544 + c];
        if (c < 512) {
            sP[j*512 + c] = v;
        } else {
            float ck = v / (v + CEPS);
            sCk[j*32 + (c - 512)] = ck;
            atomicAdd(sCkS, ck);
        }
    }
    __syncthreads();

    // ---- Phase 1: vote generation FUSED with iter-0 m-step accumulation ----
    // thread owns fixed o; k = kg + 12*i (stride 384 == 0 mod 32)
    __half* vbase = g_votes + (size_t)n * (KK*OSZ);
    {
        float macc[16], qacc[16];
        #pragma unroll
        for (int s = 0; s < 16; ++s) { macc[s] = 0.f; qacc[s] = 0.f; }
        for (int i = 0; i < 24; ++i) {
            const int k = kg + 12*i;
            const float* p = sP + k*PS;
            const float4* wv4 = (const float4*)(wts + ((size_t)(k*32 + o))*16);
            float w0[16];
            #pragma unroll
            for (int qi = 0; qi < 4; ++qi) {
                float4 t = wv4[qi];
                w0[4*qi+0]=t.x; w0[4*qi+1]=t.y; w0[4*qi+2]=t.z; w0[4*qi+3]=t.w;
            }
            const float rh = sCk[k] * 0.03125f;
            uint4* dst = (uint4*)(vbase + ((size_t)(k*32 + o))*16);
            #pragma unroll
            for (int half8 = 0; half8 < 2; ++half8) {
                float v8[8];
                #pragma unroll
                for (int ii = 0; ii < 2; ++ii) {
                    int irow = half8*2 + ii;
                    float p0=p[irow*4+0], p1=p[irow*4+1], p2=p[irow*4+2], p3=p[irow*4+3];
                    v8[4*ii+0] = p0*w0[0] + p1*w0[4] + p2*w0[8]  + p3*w0[12];
                    v8[4*ii+1] = p0*w0[1] + p1*w0[5] + p2*w0[9]  + p3*w0[13];
                    v8[4*ii+2] = p0*w0[2] + p1*w0[6] + p2*w0[10] + p3*w0[14];
                    v8[4*ii+3] = p0*w0[3] + p1*w0[7] + p2*w0[11] + p3*w0[15];
                }
                uint4 u;
                __half2 h0 = __floats2half2_rn(v8[0], v8[1]);
                __half2 h1 = __floats2half2_rn(v8[2], v8[3]);
                __half2 h2 = __floats2half2_rn(v8[4], v8[5]);
                __half2 h3 = __floats2half2_rn(v8[6], v8[7]);
                u.x = *(unsigned*)&h0; u.y = *(unsigned*)&h1;
                u.z = *(unsigned*)&h2; u.w = *(unsigned*)&h3;
                dst[half8] = u;
                #pragma unroll
                for (int s = 0; s < 8; ++s) {
                    float v = v8[s];
                    macc[half8*8 + s] += rh*v;
                    qacc[half8*8 + s] += rh*v*v;
                }
            }
        }
        #pragma unroll
        for (int s = 0; s < 16; ++s) {
            atomicAdd(&sM0[o*16 + s], macc[s]);
            atomicAdd(&sQ0[o*16 + s], qacc[s]);
        }
    }
    __syncthreads();

    // ---- stats 0 (rsum0 uniform = sum(ck)/32) ----
    stats_phase(tid, sM0, sQ0, nullptr, (*sCkS)*0.03125f, 0.0011f,
                sMean, sIv, sAct, sC, beta_u, beta_a);
    __syncthreads();

    // ---- re-zero ping buffers (sM0/sQ0 are reused by iteration 2)  [R5 bugfix] ----
    for (int i = tid; i < 1024; i += NT) sM0[i] = 0.f;   // sM0 + sQ0 contiguous
    __syncthreads();

    // ---- Two fused (e-step + m-accumulate) vote-read passes ----
    #pragma unroll 1
    for (int it = 1; it <= 2; ++it) {
        float* Mb = (it == 1) ? sM1 : sM0;
        float* Qb = (it == 1) ? sQ1 : sQ0;
        float* rs = (it == 1) ? sRs1 : sRs2;
        {
            __half2 mh[8], ivh[8];
            #pragma unroll
            for (int h = 0; h < 8; ++h) {
                mh[h]  = __floats2half2_rn(sMean[o*17 + 2*h], sMean[o*17 + 2*h+1]);
                ivh[h] = __floats2half2_rn(sIv[o*17 + 2*h],   sIv[o*17 + 2*h+1]);
            }
            const float Co = sC[o];
            float macc[16], qacc[16];
            #pragma unroll
            for (int s = 0; s < 16; ++s) { macc[s] = 0.f; qacc[s] = 0.f; }
            float racc = 0.f;
            const uint4* vr = (const uint4*)vbase;
            #pragma unroll 2
            for (int i = 0; i < 24; ++i) {
                const int k = kg + 12*i;
                const size_t ro = (size_t)(k*32 + o)*2;
                uint4 u0 = vr[ro];
                uint4 u1 = vr[ro + 1];
                float acc = 0.f;
                #pragma unroll
                for (int h = 0; h < 8; ++h) {
                    unsigned u = (h < 4) ? (&u0.x)[h] : (&u1.x)[h-4];
                    float2 f  = __half22float2(*(__half2*)&u);
                    float2 mm = __half22float2(mh[h]);
                    float2 iv = __half22float2(ivh[h]);
                    float d0 = f.x - mm.x;
                    float d1 = f.y - mm.y;
                    acc += d0*d0*iv.x + d1*d1*iv.y;
                }
                float lnap = Co - acc;
                float mx = lnap;
                #pragma unroll
                for (int off = 16; off; off >>= 1)
                    mx = fmaxf(mx, __shfl_xor_sync(0xffffffffu, mx, off));
                float e  = __expf(lnap - mx);
                float se = e;
                #pragma unroll
                for (int off = 16; off; off >>= 1)
                    se += __shfl_xor_sync(0xffffffffu, se, off);
                float rh = (e/se) * sCk[k];     // exact r*a, o-normalized
                racc += rh;
                #pragma unroll
                for (int h = 0; h < 8; ++h) {
                    unsigned u = (h < 4) ? (&u0.x)[h] : (&u1.x)[h-4];
                    float2 f = __half22float2(*(__half2*)&u);
                    macc[2*h]   += rh*f.x;
                    macc[2*h+1] += rh*f.y;
                    qacc[2*h]   += rh*f.x*f.x;
                    qacc[2*h+1] += rh*f.y*f.y;
                }
            }
            #pragma unroll
            for (int s = 0; s < 16; ++s) {
                atomicAdd(&Mb[o*16 + s], macc[s]);
                atomicAdd(&Qb[o*16 + s], qacc[s]);
            }
            atomicAdd(&rs[o], racc);
        }
        __syncthreads();

        stats_phase(tid, Mb, Qb, rs, 0.f, (it == 1) ? 0.0012f : 0.0013f,
                    sMean, sIv, sAct, sC, beta_u, beta_a);
        __syncthreads();
    }

    // ---- output: [n, 544] = concat(mean[32*16], act[32]) ----
    for (int j = tid; j < 544; j += NT) {
        if (j < 512) {
            int oo = j >> 4, s = j & 15;
            out[(size_t)n*544 + j] = sMean[oo*17 + s];
        } else {
            out[(size_t)n*544 + j] = sAct[j - 512];
        }
    }
}

extern "C" void kernel_launch(void* const* d_in, const int* in_sizes, int n_in,
                              void* d_out, int out_size)
{
    const float* x  = (const float*)d_in[0];
    const float* w  = (const float*)d_in[1];
    const float* bu = (const float*)d_in[2];
    const float* ba = (const float*)d_in[3];
    float* out = (float*)d_out;

    const int smem_bytes = 8192 * 4;   // 32 KB; 2 CTAs/SM
    cudaFuncSetAttribute(convcaps_kernel,
                         cudaFuncAttributeMaxDynamicSharedMemorySize, smem_bytes);
    convcaps_kernel<<<NPOS, NT, smem_bytes>>>(x, w, bu, ba, out);
}

// round 7
// speedup vs baseline: 1.9092x; 1.9092x over previous
#include <cuda_runtime.h>
#include <cuda_fp16.h>
#include <math.h>

#define NPOS 392
#define KK   288          // K*K*IN_CAPS
#define OC   32
#define PS   16
#define OSZ  512          // OC*PS
#define CEPS 1e-8f
#define LN2PI 1.8378770664093453f
#define NT   512          // 16 warps; 2 CTAs/SM -> 64-reg ceiling

// vote scratch (fp16): 392 * 288 * 512 * 2B = 115.6 MB
__device__ __half g_votes[(size_t)NPOS * KK * OSZ];

extern __shared__ float smem[];

// Finalize mean/var/act/C from raw sums; ZEROES Mb/Qb after reading (race-safe:
// same thread reads then writes, barrier follows outside).
__device__ __forceinline__ void stats_phase(
    int tid, float* Mb, float* Qb,
    const float* rsArr, float rsUni, float lam,
    float* sMean, float* sIv, float* sAct, float* sC,
    const float* __restrict__ beta_u, const float* __restrict__ beta_a)
{
    if (tid < 256) {
        const int o  = tid >> 3;
        const int sp = tid & 7;
        float rs  = rsArr ? rsArr[o] : rsUni;
        float irs = 1.f/(rs + CEPS);
        float s1  = rs/(rs + CEPS);
        float M0 = Mb[o*16 + 2*sp]   * irs;
        float M1 = Mb[o*16 + 2*sp+1] * irs;
        float Q0 = Qb[o*16 + 2*sp]   * irs;
        float Q1 = Qb[o*16 + 2*sp+1] * irs;
        Mb[o*16 + 2*sp] = 0.f; Mb[o*16 + 2*sp+1] = 0.f;
        Qb[o*16 + 2*sp] = 0.f; Qb[o*16 + 2*sp+1] = 0.f;
        // sum r*(v-mean)^2 = Q - mean^2*(2 - S1)   (exact EPS algebra)
        float v0 = fmaxf(Q0 - M0*M0*(2.f - s1), 0.f) + CEPS;
        float v1 = fmaxf(Q1 - M1*M1*(2.f - s1), 0.f) + CEPS;
        sMean[o*17 + 2*sp]   = M0;
        sMean[o*17 + 2*sp+1] = M1;
        sIv[o*17 + 2*sp]     = 0.5f/v0;
        sIv[o*17 + 2*sp+1]   = 0.5f/v1;
        float sl = 0.5f*(__logf(v0) + __logf(v1));
        #pragma unroll
        for (int off = 1; off < 8; off <<= 1)
            sl += __shfl_xor_sync(0xffffffffu, sl, off);
        if (sp == 0) {
            float cost = (16.f*beta_u[o] + sl) * rs;
            float z = lam * (beta_a[o] - cost);
            float a = 1.f/(1.f + __expf(-z));
            sAct[o] = a;
            sC[o]   = __logf(a) - sl - 8.f*LN2PI;
        }
    }
}

__global__ __launch_bounds__(NT, 2)
void convcaps_kernel(const float* __restrict__ x,
                     const float* __restrict__ wts,
                     const float* __restrict__ beta_u,
                     const float* __restrict__ beta_a,
                     float* __restrict__ out)
{
    const int n    = blockIdx.x;
    const int tid  = threadIdx.x;
    const int lane = tid & 31;
    const int wid  = tid >> 5;

    // ---- smem carve (~64 KB) ----
    float* sP    = smem;            // 4608  poses [k][s]
    float* sCk   = sP + KK*PS;      // 288   ck = a/(a+eps)
    float* sR    = sCk + KK;        // 9216  r_hat [k][o]
    float* sM    = sR + KK*OC;      // 512   raw M sums
    float* sQ    = sM + 512;        // 512   raw Q sums
    float* sMean = sQ + 512;        // 544   [o*17+s]
    float* sIv   = sMean + 544;     // 544
    float* sRs1  = sIv + 544;       // 32
    float* sRs2  = sRs1 + 32;       // 32
    float* sAct  = sRs2 + 32;       // 32
    float* sC    = sAct + 32;       // 32
    float* sCkS  = sC + 32;         // 1

    // ---- zero accumulators ----
    for (int i = tid; i < 1024; i += NT) sM[i] = 0.f;   // sM+sQ contiguous
    if (tid < 64) sRs1[tid] = 0.f;                      // sRs1+sRs2 contiguous
    if (tid == 64) *sCkS = 0.f;
    __syncthreads();

    // ---- Phase 0: gather input tile (reference reshape semantics) ----
    const int b = n / 49;
    const int m = n - b*49;
    for (int idx = tid; idx < 9*544; idx += NT) {
        int j   = idx / 544;
        int c   = idx - j*544;
        int t9  = 9*m + j;
        int khw = t9 / 49;
        int oyx = t9 - khw*49;
        int oy  = oyx / 7;
        int ox  = oyx - oy*7;
        int kh  = khw / 3;
        int kw  = khw - kh*3;
        int h   = 2*oy + kh;
        int w   = 2*ox + kw;
        float v = x[(size_t)(((b*16 + h)*16) + w)*544 + c];
        if (c < 512) {
            sP[j*512 + c] = v;
        } else {
            float ck = v / (v + CEPS);
            sCk[j*32 + (c - 512)] = ck;
            atomicAdd(sCkS, ck);
        }
    }
    __syncthreads();

    // ---- Phase 1: HALF-ROW vote generation fused with iter-0 m-accumulation ----
    // thread = (o, rhalf, kg): o fixed -> 8+8 register accumulators only.
    __half* vbase = g_votes + (size_t)n * (KK*OSZ);
    {
        const int o     = tid & 31;
        const int rhalf = (tid >> 5) & 1;     // owns s in [8*rhalf, 8*rhalf+8)
        const int kg    = tid >> 6;           // 0..7
        float macc[8], qacc[8];
        #pragma unroll
        for (int s = 0; s < 8; ++s) { macc[s] = 0.f; qacc[s] = 0.f; }
        for (int i = 0; i < 36; ++i) {
            const int k = kg + 8*i;
            const float* p = sP + k*PS + rhalf*8;   // rows i2=0,1 of this half
            const float4* wv4 = (const float4*)(wts + ((size_t)(k*32 + o))*16);
            float w0[16];
            #pragma unroll
            for (int qi = 0; qi < 4; ++qi) {
                float4 t = wv4[qi];
                w0[4*qi+0]=t.x; w0[4*qi+1]=t.y; w0[4*qi+2]=t.z; w0[4*qi+3]=t.w;
            }
            const float rh = sCk[k] * 0.03125f;
            float v8[8];
            #pragma unroll
            for (int i2 = 0; i2 < 2; ++i2) {
                float p0=p[i2*4+0], p1=p[i2*4+1], p2=p[i2*4+2], p3=p[i2*4+3];
                v8[4*i2+0] = p0*w0[0] + p1*w0[4] + p2*w0[8]  + p3*w0[12];
                v8[4*i2+1] = p0*w0[1] + p1*w0[5] + p2*w0[9]  + p3*w0[13];
                v8[4*i2+2] = p0*w0[2] + p1*w0[6] + p2*w0[10] + p3*w0[14];
                v8[4*i2+3] = p0*w0[3] + p1*w0[7] + p2*w0[11] + p3*w0[15];
            }
            __half2 h0 = __floats2half2_rn(v8[0], v8[1]);
            __half2 h1 = __floats2half2_rn(v8[2], v8[3]);
            __half2 h2 = __floats2half2_rn(v8[4], v8[5]);
            __half2 h3 = __floats2half2_rn(v8[6], v8[7]);
            uint4 u;
            u.x = *(unsigned*)&h0; u.y = *(unsigned*)&h1;
            u.z = *(unsigned*)&h2; u.w = *(unsigned*)&h3;
            *(uint4*)(vbase + ((size_t)(k*32 + o))*16 + rhalf*8) = u;
            #pragma unroll
            for (int s = 0; s < 8; ++s) {
                macc[s] += rh*v8[s];
                qacc[s] += rh*v8[s]*v8[s];
            }
        }
        #pragma unroll
        for (int s = 0; s < 8; ++s) {
            atomicAdd(&sM[o*16 + rhalf*8 + s], macc[s]);
            atomicAdd(&sQ[o*16 + rhalf*8 + s], qacc[s]);
        }
    }
    __syncthreads();

    // ---- stats 0 (rsum0 uniform = sum(ck)/32); zeroes sM/sQ after read ----
    stats_phase(tid, sM, sQ, nullptr, (*sCkS)*0.03125f, 0.0011f,
                sMean, sIv, sAct, sC, beta_u, beta_a);
    __syncthreads();

    // ---- iterations 1,2: separate e-pass then m-pass (both low-register) ----
    #pragma unroll 1
    for (int it = 1; it <= 2; ++it) {
        float* rs = (it == 1) ? sRs1 : sRs2;

        // e-pass: r_hat = softmax_o(lnap) * ck, write sR, accumulate rsum
        {
            __half2 mh[8], ivh[8];
            #pragma unroll
            for (int h = 0; h < 8; ++h) {
                mh[h]  = __floats2half2_rn(sMean[lane*17 + 2*h], sMean[lane*17 + 2*h+1]);
                ivh[h] = __floats2half2_rn(sIv[lane*17 + 2*h],   sIv[lane*17 + 2*h+1]);
            }
            const float Co = sC[lane];
            const uint4* vr = (const uint4*)vbase;
            float racc = 0.f;
            for (int k = wid; k < KK; k += 16) {
                uint4 u0 = vr[(size_t)(k*32 + lane)*2];
                uint4 u1 = vr[(size_t)(k*32 + lane)*2 + 1];
                float acc = 0.f;
                #pragma unroll
                for (int h = 0; h < 8; ++h) {
                    unsigned u = (h < 4) ? (&u0.x)[h] : (&u1.x)[h-4];
                    float2 f  = __half22float2(*(__half2*)&u);
                    float2 mm = __half22float2(mh[h]);
                    float2 iv = __half22float2(ivh[h]);
                    float d0 = f.x - mm.x;
                    float d1 = f.y - mm.y;
                    acc += d0*d0*iv.x + d1*d1*iv.y;
                }
                float lnap = Co - acc;
                float mx = lnap;
                #pragma unroll
                for (int off = 16; off; off >>= 1)
                    mx = fmaxf(mx, __shfl_xor_sync(0xffffffffu, mx, off));
                float e  = __expf(lnap - mx);
                float se = e;
                #pragma unroll
                for (int off = 16; off; off >>= 1)
                    se += __shfl_xor_sync(0xffffffffu, se, off);
                float rh = (e/se) * sCk[k];   // exact r*a, o-normalized
                sR[k*32 + lane] = rh;
                racc += rh;
            }
            atomicAdd(&rs[lane], racc);
        }
        __syncthreads();

        // m-pass: thread=(khalf, o, sp) half2 strided reads; raw sums -> sM/sQ
        {
            const int khalf = tid >> 8;
            const int idx   = tid & 255;
            const int o     = idx >> 3;
            const int sp    = idx & 7;
            const __half2* vp2 = (const __half2*)vbase + idx;
            const float* rp0 = sR + o;
            float m0 = 0.f, m1 = 0.f, q0 = 0.f, q1 = 0.f;
            const int k0 = khalf * 144;
            #pragma unroll 4
            for (int k = k0; k < k0 + 144; ++k) {
                float2 v = __half22float2(vp2[(size_t)k*256]);
                float r  = rp0[k*32];
                m0 += r*v.x; m1 += r*v.y;
                q0 += r*v.x*v.x; q1 += r*v.y*v.y;
            }
            atomicAdd(&sM[o*16 + 2*sp],   m0);
            atomicAdd(&sM[o*16 + 2*sp+1], m1);
            atomicAdd(&sQ[o*16 + 2*sp],   q0);
            atomicAdd(&sQ[o*16 + 2*sp+1], q1);
        }
        __syncthreads();

        stats_phase(tid, sM, sQ, rs, 0.f, (it == 1) ? 0.0012f : 0.0013f,
                    sMean, sIv, sAct, sC, beta_u, beta_a);
        __syncthreads();
    }

    // ---- output: [n, 544] = concat(mean[32*16], act[32]) ----
    {
        int o = tid >> 4, s = tid & 15;
        out[(size_t)n*544 + tid] = sMean[o*17 + s];
        if (tid < 32)
            out[(size_t)n*544 + 512 + tid] = sAct[tid];
    }
}

extern "C" void kernel_launch(void* const* d_in, const int* in_sizes, int n_in,
                              void* d_out, int out_size)
{
    const float* x  = (const float*)d_in[0];
    const float* w  = (const float*)d_in[1];
    const float* bu = (const float*)d_in[2];
    const float* ba = (const float*)d_in[3];
    float* out = (float*)d_out;

    const int smem_bytes = 16384 * 4;   // 64 KB -> 2 CTAs/SM
    cudaFuncSetAttribute(convcaps_kernel,
                         cudaFuncAttributeMaxDynamicSharedMemorySize, smem_bytes);
    convcaps_kernel<<<NPOS, NT, smem_bytes>>>(x, w, bu, ba, out);
}

// round 8
// speedup vs baseline: 2.3985x; 1.2563x over previous
#include <cuda_runtime.h>
#include <cuda_fp16.h>
#include <math.h>

#define NPOS 392
#define KK   288          // K*K*IN_CAPS
#define OC   32
#define PS   16
#define OSZ  512          // OC*PS
#define CEPS 1e-8f
#define LN2PI 1.8378770664093453f
#define NT   512          // 16 warps; 2 CTAs/SM

// vote scratch (fp16): 392 * 288 * 512 * 2B = 115.6 MB
__device__ __half g_votes[(size_t)NPOS * KK * OSZ];

extern __shared__ float smem[];

// Finalize mean/var/act/C from raw sums; zeroes Mb/Qb after reading (same
// thread reads-then-writes; barrier follows outside -> race-free).
__device__ __forceinline__ void stats_phase(
    int tid, float* Mb, float* Qb,
    const float* rsArr, float rsUni, float lam,
    float* sMean, float* sIv, float* sAct, float* sC,
    const float* __restrict__ beta_u, const float* __restrict__ beta_a)
{
    if (tid < 256) {
        const int o  = tid >> 3;
        const int sp = tid & 7;
        float rs  = rsArr ? rsArr[o] : rsUni;
        float irs = 1.f/(rs + CEPS);
        float s1  = rs/(rs + CEPS);
        float M0 = Mb[o*16 + 2*sp]   * irs;
        float M1 = Mb[o*16 + 2*sp+1] * irs;
        float Q0 = Qb[o*16 + 2*sp]   * irs;
        float Q1 = Qb[o*16 + 2*sp+1] * irs;
        Mb[o*16 + 2*sp] = 0.f; Mb[o*16 + 2*sp+1] = 0.f;
        Qb[o*16 + 2*sp] = 0.f; Qb[o*16 + 2*sp+1] = 0.f;
        // sum r*(v-mean)^2 = Q - mean^2*(2 - S1)   (exact EPS algebra)
        float v0 = fmaxf(Q0 - M0*M0*(2.f - s1), 0.f) + CEPS;
        float v1 = fmaxf(Q1 - M1*M1*(2.f - s1), 0.f) + CEPS;
        sMean[o*17 + 2*sp]   = M0;
        sMean[o*17 + 2*sp+1] = M1;
        sIv[o*17 + 2*sp]     = 0.5f/v0;
        sIv[o*17 + 2*sp+1]   = 0.5f/v1;
        float sl = 0.5f*(__logf(v0) + __logf(v1));
        #pragma unroll
        for (int off = 1; off < 8; off <<= 1)
            sl += __shfl_xor_sync(0xffffffffu, sl, off);
        if (sp == 0) {
            float cost = (16.f*beta_u[o] + sl) * rs;
            float z = lam * (beta_a[o] - cost);
            float a = 1.f/(1.f + __expf(-z));
            sAct[o] = a;
            sC[o]   = __logf(a) - sl - 8.f*LN2PI;
        }
    }
}

__global__ __launch_bounds__(NT, 2)
void convcaps_kernel(const float* __restrict__ x,
                     const float* __restrict__ wts,
                     const float* __restrict__ beta_u,
                     const float* __restrict__ beta_a,
                     float* __restrict__ out)
{
    const int n    = blockIdx.x;
    const int tid  = threadIdx.x;
    const int lane = tid & 31;
    const int wid  = tid >> 5;

    // ---- smem carve (~64 KB) ----
    float* sP    = smem;            // 4608  poses [k][s]
    float* sCk   = sP + KK*PS;      // 288   ck = a/(a+eps)
    float* sR    = sCk + KK;        // 9216  r_hat [k][o]
    float* sM    = sR + KK*OC;      // 512   raw M sums
    float* sQ    = sM + 512;        // 512   raw Q sums
    float* sMean = sQ + 512;        // 544   [o*17+s]
    float* sIv   = sMean + 544;     // 544
    float* sRs1  = sIv + 544;       // 32
    float* sRs2  = sRs1 + 32;       // 32
    float* sAct  = sRs2 + 32;       // 32
    float* sC    = sAct + 32;       // 32
    float* sCkS  = sC + 32;         // 1

    // ---- zero accumulators ----
    for (int i = tid; i < 1024; i += NT) sM[i] = 0.f;   // sM+sQ contiguous
    if (tid < 64) sRs1[tid] = 0.f;                      // sRs1+sRs2 contiguous
    if (tid == 64) *sCkS = 0.f;
    __syncthreads();

    // ---- Phase 0: gather input tile (reference reshape semantics) ----
    const int b = n / 49;
    const int m = n - b*49;
    for (int idx = tid; idx < 9*544; idx += NT) {
        int j   = idx / 544;
        int c   = idx - j*544;
        int t9  = 9*m + j;
        int khw = t9 / 49;
        int oyx = t9 - khw*49;
        int oy  = oyx / 7;
        int ox  = oyx - oy*7;
        int kh  = khw / 3;
        int kw  = khw - kh*3;
        int h   = 2*oy + kh;
        int w   = 2*ox + kw;
        float v = x[(size_t)(((b*16 + h)*16) + w)*544 + c];
        if (c < 512) {
            sP[j*512 + c] = v;
        } else {
            float ck = v / (v + CEPS);
            sCk[j*32 + (c - 512)] = ck;
            atomicAdd(sCkS, ck);
        }
    }
    __syncthreads();

    // ---- Phase 1: simple vote gen  v[k,o,:] = p[k] (4x4) @ W[k,o] (4x4) ----
    __half* vbase = g_votes + (size_t)n * (KK*OSZ);
    for (int pair = tid; pair < KK*OC; pair += NT) {
        int k = pair >> 5;
        const float* p = sP + k*PS;
        const float4* wv4 = (const float4*)(wts + (size_t)pair*16);
        float w0[16];
        #pragma unroll
        for (int qi = 0; qi < 4; ++qi) {
            float4 t = wv4[qi];
            w0[4*qi+0]=t.x; w0[4*qi+1]=t.y; w0[4*qi+2]=t.z; w0[4*qi+3]=t.w;
        }
        __half2 hh[8];
        #pragma unroll
        for (int i = 0; i < 4; ++i) {
            float p0=p[i*4+0], p1=p[i*4+1], p2=p[i*4+2], p3=p[i*4+3];
            float r0 = p0*w0[0] + p1*w0[4] + p2*w0[8]  + p3*w0[12];
            float r1 = p0*w0[1] + p1*w0[5] + p2*w0[9]  + p3*w0[13];
            float r2 = p0*w0[2] + p1*w0[6] + p2*w0[10] + p3*w0[14];
            float r3 = p0*w0[3] + p1*w0[7] + p2*w0[11] + p3*w0[15];
            hh[2*i+0] = __floats2half2_rn(r0, r1);
            hh[2*i+1] = __floats2half2_rn(r2, r3);
        }
        uint4* dst = (uint4*)(vbase + (size_t)pair*16);
        uint4 u0, u1;
        u0.x = *(unsigned*)&hh[0]; u0.y = *(unsigned*)&hh[1];
        u0.z = *(unsigned*)&hh[2]; u0.w = *(unsigned*)&hh[3];
        u1.x = *(unsigned*)&hh[4]; u1.y = *(unsigned*)&hh[5];
        u1.z = *(unsigned*)&hh[6]; u1.w = *(unsigned*)&hh[7];
        dst[0] = u0; dst[1] = u1;
    }
    __syncthreads();

    // ---- m-passes + e-passes, 3 EM iterations ----
    // m-pass layout: thread = (kq 0..3, ix 0..127); ix covers uint2 (4 halves)
    //   o = ix>>2, s base = 4*(ix&3); 72 k per quarter.
    #pragma unroll 1
    for (int it = 0; it <= 2; ++it) {
        // (m) accumulate raw M/Q sums over k
        {
            const int kq = tid >> 7;
            const int ix = tid & 127;
            const int o  = ix >> 2;
            const int sb = 4*(ix & 3);
            const uint2* vp = (const uint2*)((const char*)vbase + ix*8);
            float m0=0.f,m1=0.f,m2=0.f,m3=0.f,q0=0.f,q1=0.f,q2=0.f,q3=0.f;
            const int k0 = kq * 72;
            if (it == 0) {
                #pragma unroll 4
                for (int k = k0; k < k0 + 72; ++k) {
                    uint2 u = vp[(size_t)k*128];
                    float2 va = __half22float2(*(__half2*)&u.x);
                    float2 vb = __half22float2(*(__half2*)&u.y);
                    float r = sCk[k] * 0.03125f;
                    m0 += r*va.x; m1 += r*va.y; m2 += r*vb.x; m3 += r*vb.y;
                    q0 += r*va.x*va.x; q1 += r*va.y*va.y;
                    q2 += r*vb.x*vb.x; q3 += r*vb.y*vb.y;
                }
            } else {
                const float* rp0 = sR + o;
                #pragma unroll 4
                for (int k = k0; k < k0 + 72; ++k) {
                    uint2 u = vp[(size_t)k*128];
                    float2 va = __half22float2(*(__half2*)&u.x);
                    float2 vb = __half22float2(*(__half2*)&u.y);
                    float r = rp0[k*32];
                    m0 += r*va.x; m1 += r*va.y; m2 += r*vb.x; m3 += r*vb.y;
                    q0 += r*va.x*va.x; q1 += r*va.y*va.y;
                    q2 += r*vb.x*vb.x; q3 += r*vb.y*vb.y;
                }
            }
            atomicAdd(&sM[o*16 + sb + 0], m0);
            atomicAdd(&sM[o*16 + sb + 1], m1);
            atomicAdd(&sM[o*16 + sb + 2], m2);
            atomicAdd(&sM[o*16 + sb + 3], m3);
            atomicAdd(&sQ[o*16 + sb + 0], q0);
            atomicAdd(&sQ[o*16 + sb + 1], q1);
            atomicAdd(&sQ[o*16 + sb + 2], q2);
            atomicAdd(&sQ[o*16 + sb + 3], q3);
        }
        __syncthreads();

        // (stats) finalize; zeroes sM/sQ for the next m-pass
        {
            const float* rsArr = (it == 0) ? nullptr : ((it == 1) ? sRs1 : sRs2);
            const float rsUni  = (it == 0) ? (*sCkS)*0.03125f : 0.f;
            const float lam    = 0.0011f + 0.0001f*it;
            stats_phase(tid, sM, sQ, rsArr, rsUni, lam,
                        sMean, sIv, sAct, sC, beta_u, beta_a);
        }
        __syncthreads();

        if (it == 2) break;

        // (e) r_hat = softmax_o(lnap) * ck -> sR; accumulate rsum
        {
            float* rs = (it == 0) ? sRs1 : sRs2;
            __half2 mh[8], ivh[8];
            #pragma unroll
            for (int h = 0; h < 8; ++h) {
                mh[h]  = __floats2half2_rn(sMean[lane*17 + 2*h], sMean[lane*17 + 2*h+1]);
                ivh[h] = __floats2half2_rn(sIv[lane*17 + 2*h],   sIv[lane*17 + 2*h+1]);
            }
            const float Co = sC[lane];
            const uint4* vr = (const uint4*)vbase;
            float racc = 0.f;
            for (int k = wid; k < KK; k += 16) {
                uint4 u0 = vr[(size_t)(k*32 + lane)*2];
                uint4 u1 = vr[(size_t)(k*32 + lane)*2 + 1];
                float acc = 0.f;
                #pragma unroll
                for (int h = 0; h < 8; ++h) {
                    unsigned u = (h < 4) ? (&u0.x)[h] : (&u1.x)[h-4];
                    float2 f  = __half22float2(*(__half2*)&u);
                    float2 mm = __half22float2(mh[h]);
                    float2 iv = __half22float2(ivh[h]);
                    float d0 = f.x - mm.x;
                    float d1 = f.y - mm.y;
                    acc += d0*d0*iv.x + d1*d1*iv.y;
                }
                float lnap = Co - acc;
                float mx = lnap;
                #pragma unroll
                for (int off = 16; off; off >>= 1)
                    mx = fmaxf(mx, __shfl_xor_sync(0xffffffffu, mx, off));
                float e  = __expf(lnap - mx);
                float se = e;
                #pragma unroll
                for (int off = 16; off; off >>= 1)
                    se += __shfl_xor_sync(0xffffffffu, se, off);
                float rh = (e/se) * sCk[k];   // exact r*a, o-normalized
                sR[k*32 + lane] = rh;
                racc += rh;
            }
            atomicAdd(&rs[lane], racc);
        }
        __syncthreads();
    }

    // ---- output: [n, 544] = concat(mean[32*16], act[32]) ----
    {
        int o = tid >> 4, s = tid & 15;
        out[(size_t)n*544 + tid] = sMean[o*17 + s];
        if (tid < 32)
            out[(size_t)n*544 + 512 + tid] = sAct[tid];
    }
}

extern "C" void kernel_launch(void* const* d_in, const int* in_sizes, int n_in,
                              void* d_out, int out_size)
{
    const float* x  = (const float*)d_in[0];
    const float* w  = (const float*)d_in[1];
    const float* bu = (const float*)d_in[2];
    const float* ba = (const float*)d_in[3];
    float* out = (float*)d_out;

    // 80 KB request pins occupancy at exactly 2 CTAs/SM (L2-resident vote wave)
    const int smem_bytes = 81920;
    cudaFuncSetAttribute(convcaps_kernel,
                         cudaFuncAttributeMaxDynamicSharedMemorySize, smem_bytes);
    convcaps_kernel<<<NPOS, NT, smem_bytes>>>(x, w, bu, ba, out);
}

// round 9
// speedup vs baseline: 2.5023x; 1.0433x over previous
#include <cuda_runtime.h>
#include <cuda_fp16.h>
#include <math.h>

#define NPOS 392
#define KK   288          // K*K*IN_CAPS
#define OC   32
#define PS   16
#define OSZ  512          // OC*PS
#define CEPS 1e-8f
#define LN2PI 1.8378770664093453f
#define NT   512          // 16 warps; 2 CTAs/SM

// vote scratch (fp16): 392 * 288 * 512 * 2B = 115.6 MB
__device__ __half g_votes[(size_t)NPOS * KK * OSZ];

extern __shared__ float smem[];

// Finalize mean/var/act/C from raw sums; zeroes Mb/Qb after reading (same
// thread reads-then-writes; barrier follows outside -> race-free).
__device__ __forceinline__ void stats_phase(
    int tid, float* Mb, float* Qb,
    const float* rsArr, float rsUni, float lam,
    float* sMean, float* sIv, float* sAct, float* sC,
    const float* __restrict__ beta_u, const float* __restrict__ beta_a)
{
    if (tid < 256) {
        const int o  = tid >> 3;
        const int sp = tid & 7;
        float rs  = rsArr ? rsArr[o] : rsUni;
        float irs = 1.f/(rs + CEPS);
        float s1  = rs/(rs + CEPS);
        float M0 = Mb[o*16 + 2*sp]   * irs;
        float M1 = Mb[o*16 + 2*sp+1] * irs;
        float Q0 = Qb[o*16 + 2*sp]   * irs;
        float Q1 = Qb[o*16 + 2*sp+1] * irs;
        Mb[o*16 + 2*sp] = 0.f; Mb[o*16 + 2*sp+1] = 0.f;
        Qb[o*16 + 2*sp] = 0.f; Qb[o*16 + 2*sp+1] = 0.f;
        // sum r*(v-mean)^2 = Q - mean^2*(2 - S1)   (exact EPS algebra)
        float v0 = fmaxf(Q0 - M0*M0*(2.f - s1), 0.f) + CEPS;
        float v1 = fmaxf(Q1 - M1*M1*(2.f - s1), 0.f) + CEPS;
        sMean[o*17 + 2*sp]   = M0;
        sMean[o*17 + 2*sp+1] = M1;
        sIv[o*17 + 2*sp]     = 0.5f/v0;
        sIv[o*17 + 2*sp+1]   = 0.5f/v1;
        float sl = 0.5f*(__logf(v0) + __logf(v1));
        #pragma unroll
        for (int off = 1; off < 8; off <<= 1)
            sl += __shfl_xor_sync(0xffffffffu, sl, off);
        if (sp == 0) {
            float cost = (16.f*beta_u[o] + sl) * rs;
            float z = lam * (beta_a[o] - cost);
            float a = 1.f/(1.f + __expf(-z));
            sAct[o] = a;
            sC[o]   = __logf(a) - sl - 8.f*LN2PI;
        }
    }
}

__global__ __launch_bounds__(NT, 2)
void convcaps_kernel(const float* __restrict__ x,
                     const float* __restrict__ wts,
                     const float* __restrict__ beta_u,
                     const float* __restrict__ beta_a,
                     float* __restrict__ out)
{
    const int n    = blockIdx.x;
    const int tid  = threadIdx.x;
    const int lane = tid & 31;
    const int wid  = tid >> 5;

    // ---- smem carve (~64 KB) ----
    float* sP    = smem;            // 4608  poses [k][s]
    float* sCk   = sP + KK*PS;      // 288   ck = a/(a+eps)
    float* sR    = sCk + KK;        // 9216  r_hat [k][o]
    float* sM    = sR + KK*OC;      // 512   raw M sums
    float* sQ    = sM + 512;        // 512   raw Q sums
    float* sMean = sQ + 512;        // 544   [o*17+s]
    float* sIv   = sMean + 544;     // 544
    float* sRs1  = sIv + 544;       // 32
    float* sRs2  = sRs1 + 32;       // 32
    float* sAct  = sRs2 + 32;       // 32
    float* sC    = sAct + 32;       // 32
    float* sCkS  = sC + 32;         // 1

    // ---- zero accumulators ----
    for (int i = tid; i < 1024; i += NT) sM[i] = 0.f;   // sM+sQ contiguous
    if (tid < 64) sRs1[tid] = 0.f;                      // sRs1+sRs2 contiguous
    if (tid == 64) *sCkS = 0.f;
    __syncthreads();

    // ---- Phase 0: gather input tile (reference reshape semantics) ----
    const int b = n / 49;
    const int m = n - b*49;
    for (int idx = tid; idx < 9*544; idx += NT) {
        int j   = idx / 544;
        int c   = idx - j*544;
        int t9  = 9*m + j;
        int khw = t9 / 49;
        int oyx = t9 - khw*49;
        int oy  = oyx / 7;
        int ox  = oyx - oy*7;
        int kh  = khw / 3;
        int kw  = khw - kh*3;
        int h   = 2*oy + kh;
        int w   = 2*ox + kw;
        float v = x[(size_t)(((b*16 + h)*16) + w)*544 + c];
        if (c < 512) {
            sP[j*512 + c] = v;
        } else {
            float ck = v / (v + CEPS);
            sCk[j*32 + (c - 512)] = ck;
            atomicAdd(sCkS, ck);
        }
    }
    __syncthreads();

    // ---- Phase 1: simple vote gen  v[k,o,:] = p[k] (4x4) @ W[k,o] (4x4) ----
    __half* vbase = g_votes + (size_t)n * (KK*OSZ);
    for (int pair = tid; pair < KK*OC; pair += NT) {
        int k = pair >> 5;
        const float* p = sP + k*PS;
        const float4* wv4 = (const float4*)(wts + (size_t)pair*16);
        float w0[16];
        #pragma unroll
        for (int qi = 0; qi < 4; ++qi) {
            float4 t = wv4[qi];
            w0[4*qi+0]=t.x; w0[4*qi+1]=t.y; w0[4*qi+2]=t.z; w0[4*qi+3]=t.w;
        }
        __half2 hh[8];
        #pragma unroll
        for (int i = 0; i < 4; ++i) {
            float p0=p[i*4+0], p1=p[i*4+1], p2=p[i*4+2], p3=p[i*4+3];
            float r0 = p0*w0[0] + p1*w0[4] + p2*w0[8]  + p3*w0[12];
            float r1 = p0*w0[1] + p1*w0[5] + p2*w0[9]  + p3*w0[13];
            float r2 = p0*w0[2] + p1*w0[6] + p2*w0[10] + p3*w0[14];
            float r3 = p0*w0[3] + p1*w0[7] + p2*w0[11] + p3*w0[15];
            hh[2*i+0] = __floats2half2_rn(r0, r1);
            hh[2*i+1] = __floats2half2_rn(r2, r3);
        }
        uint4* dst = (uint4*)(vbase + (size_t)pair*16);
        uint4 u0, u1;
        u0.x = *(unsigned*)&hh[0]; u0.y = *(unsigned*)&hh[1];
        u0.z = *(unsigned*)&hh[2]; u0.w = *(unsigned*)&hh[3];
        u1.x = *(unsigned*)&hh[4]; u1.y = *(unsigned*)&hh[5];
        u1.z = *(unsigned*)&hh[6]; u1.w = *(unsigned*)&hh[7];
        dst[0] = u0; dst[1] = u1;
    }
    __syncthreads();

    // ---- m-passes + e-passes, 3 EM iterations ----
    #pragma unroll 1
    for (int it = 0; it <= 2; ++it) {
        // (m) accumulate raw M/Q sums over k
        {
            const int kq = tid >> 7;
            const int ix = tid & 127;
            const int o  = ix >> 2;
            const int sb = 4*(ix & 3);
            const uint2* vp = (const uint2*)((const char*)vbase + ix*8);
            float m0=0.f,m1=0.f,m2=0.f,m3=0.f,q0=0.f,q1=0.f,q2=0.f,q3=0.f;
            const int k0 = kq * 72;
            if (it == 0) {
                #pragma unroll 8
                for (int k = k0; k < k0 + 72; ++k) {
                    uint2 u = vp[(size_t)k*128];
                    float2 va = __half22float2(*(__half2*)&u.x);
                    float2 vb = __half22float2(*(__half2*)&u.y);
                    float r = sCk[k] * 0.03125f;
                    m0 += r*va.x; m1 += r*va.y; m2 += r*vb.x; m3 += r*vb.y;
                    q0 += r*va.x*va.x; q1 += r*va.y*va.y;
                    q2 += r*vb.x*vb.x; q3 += r*vb.y*vb.y;
                }
            } else {
                const float* rp0 = sR + o;
                #pragma unroll 8
                for (int k = k0; k < k0 + 72; ++k) {
                    uint2 u = vp[(size_t)k*128];
                    float2 va = __half22float2(*(__half2*)&u.x);
                    float2 vb = __half22float2(*(__half2*)&u.y);
                    float r = rp0[k*32];
                    m0 += r*va.x; m1 += r*va.y; m2 += r*vb.x; m3 += r*vb.y;
                    q0 += r*va.x*va.x; q1 += r*va.y*va.y;
                    q2 += r*vb.x*vb.x; q3 += r*vb.y*vb.y;
                }
            }
            atomicAdd(&sM[o*16 + sb + 0], m0);
            atomicAdd(&sM[o*16 + sb + 1], m1);
            atomicAdd(&sM[o*16 + sb + 2], m2);
            atomicAdd(&sM[o*16 + sb + 3], m3);
            atomicAdd(&sQ[o*16 + sb + 0], q0);
            atomicAdd(&sQ[o*16 + sb + 1], q1);
            atomicAdd(&sQ[o*16 + sb + 2], q2);
            atomicAdd(&sQ[o*16 + sb + 3], q3);
        }
        __syncthreads();

        // (stats) finalize; zeroes sM/sQ for the next m-pass
        {
            const float* rsArr = (it == 0) ? nullptr : ((it == 1) ? sRs1 : sRs2);
            const float rsUni  = (it == 0) ? (*sCkS)*0.03125f : 0.f;
            const float lam    = 0.0011f + 0.0001f*it;
            stats_phase(tid, sM, sQ, rsArr, rsUni, lam,
                        sMean, sIv, sAct, sC, beta_u, beta_a);
        }
        __syncthreads();

        if (it == 2) break;

        // (e) r_hat = softmax_o(lnap) * ck -> sR; 2-way k-interleave for ILP
        {
            float* rs = (it == 0) ? sRs1 : sRs2;
            __half2 mh[8], ivh[8];
            #pragma unroll
            for (int h = 0; h < 8; ++h) {
                mh[h]  = __floats2half2_rn(sMean[lane*17 + 2*h], sMean[lane*17 + 2*h+1]);
                ivh[h] = __floats2half2_rn(sIv[lane*17 + 2*h],   sIv[lane*17 + 2*h+1]);
            }
            const float Co = sC[lane];
            const uint4* vr = (const uint4*)vbase;
            float racc = 0.f;
            #pragma unroll 1
            for (int i = 0; i < 9; ++i) {
                const int ka = wid + 32*i;
                const int kb = ka + 16;
                uint4 a0 = vr[(size_t)(ka*32 + lane)*2];
                uint4 a1 = vr[(size_t)(ka*32 + lane)*2 + 1];
                uint4 b0 = vr[(size_t)(kb*32 + lane)*2];
                uint4 b1 = vr[(size_t)(kb*32 + lane)*2 + 1];
                float accA = 0.f, accB = 0.f;
                #pragma unroll
                for (int h = 0; h < 8; ++h) {
                    float2 mm = __half22float2(mh[h]);
                    float2 iv = __half22float2(ivh[h]);
                    unsigned ua = (h < 4) ? (&a0.x)[h] : (&a1.x)[h-4];
                    float2 fa = __half22float2(*(__half2*)&ua);
                    float dA0 = fa.x - mm.x, dA1 = fa.y - mm.y;
                    accA += dA0*dA0*iv.x + dA1*dA1*iv.y;
                    unsigned ub = (h < 4) ? (&b0.x)[h] : (&b1.x)[h-4];
                    float2 fb = __half22float2(*(__half2*)&ub);
                    float dB0 = fb.x - mm.x, dB1 = fb.y - mm.y;
                    accB += dB0*dB0*iv.x + dB1*dB1*iv.y;
                }
                float lnA = Co - accA;
                float lnB = Co - accB;
                float mxA = lnA, mxB = lnB;
                #pragma unroll
                for (int off = 16; off; off >>= 1) {
                    mxA = fmaxf(mxA, __shfl_xor_sync(0xffffffffu, mxA, off));
                    mxB = fmaxf(mxB, __shfl_xor_sync(0xffffffffu, mxB, off));
                }
                float eA = __expf(lnA - mxA);
                float eB = __expf(lnB - mxB);
                float sA = eA, sB = eB;
                #pragma unroll
                for (int off = 16; off; off >>= 1) {
                    sA += __shfl_xor_sync(0xffffffffu, sA, off);
                    sB += __shfl_xor_sync(0xffffffffu, sB, off);
                }
                float rA = (eA/sA) * sCk[ka];   // exact r*a, o-normalized
                float rB = (eB/sB) * sCk[kb];
                sR[ka*32 + lane] = rA;
                sR[kb*32 + lane] = rB;
                racc += rA + rB;
            }
            atomicAdd(&rs[lane], racc);
        }
        __syncthreads();
    }

    // ---- output: [n, 544] = concat(mean[32*16], act[32]) ----
    {
        int o = tid >> 4, s = tid & 15;
        out[(size_t)n*544 + tid] = sMean[o*17 + s];
        if (tid < 32)
            out[(size_t)n*544 + 512 + tid] = sAct[tid];
    }
}

extern "C" void kernel_launch(void* const* d_in, const int* in_sizes, int n_in,
                              void* d_out, int out_size)
{
    const float* x  = (const float*)d_in[0];
    const float* w  = (const float*)d_in[1];
    const float* bu = (const float*)d_in[2];
    const float* ba = (const float*)d_in[3];
    float* out = (float*)d_out;

    // 80 KB request pins occupancy at exactly 2 CTAs/SM (L2-resident vote wave)
    const int smem_bytes = 81920;
    cudaFuncSetAttribute(convcaps_kernel,
                         cudaFuncAttributeMaxDynamicSharedMemorySize, smem_bytes);
    convcaps_kernel<<<NPOS, NT, smem_bytes>>>(x, w, bu, ba, out);
}